// round 1
// baseline (speedup 1.0000x reference)
#include <cuda_runtime.h>
#include <math.h>

#define NPTS 8192
#define DIM  256

// Scratch (device globals — no allocation allowed in kernel_launch)
__device__ float g_c2[NPTS];
__device__ float g_s2[NPTS];
__device__ float g_rowsum[NPTS];
__device__ float g_colsum[NPTS];
__device__ float g_diag;

// ---------------------------------------------------------------------------
// Zero accumulators (must run every launch: graph replays)
// ---------------------------------------------------------------------------
__global__ void dcl_init_kernel() {
    int i = blockIdx.x * blockDim.x + threadIdx.x;
    if (i < NPTS) {
        g_rowsum[i] = 0.0f;
        g_colsum[i] = 0.0f;
    }
    if (i == 0) g_diag = 0.0f;
}

// ---------------------------------------------------------------------------
// Row norms: one warp per row, both tensors
// ---------------------------------------------------------------------------
__global__ void dcl_norms_kernel(const float* __restrict__ C,
                                 const float* __restrict__ S) {
    int warp = threadIdx.x >> 5;
    int lane = threadIdx.x & 31;
    int row  = blockIdx.x * 8 + warp;

    const float4* c4 = (const float4*)(C + (size_t)row * DIM);
    const float4* s4 = (const float4*)(S + (size_t)row * DIM);

    float cs = 0.0f, ss = 0.0f;
#pragma unroll
    for (int t = 0; t < 2; t++) {
        float4 v = c4[lane + t * 32];
        cs += v.x * v.x + v.y * v.y + v.z * v.z + v.w * v.w;
        float4 w = s4[lane + t * 32];
        ss += w.x * w.x + w.y * w.y + w.z * w.z + w.w * w.w;
    }
#pragma unroll
    for (int m = 16; m >= 1; m >>= 1) {
        cs += __shfl_xor_sync(0xffffffffu, cs, m);
        ss += __shfl_xor_sync(0xffffffffu, ss, m);
    }
    if (lane == 0) {
        g_c2[row] = cs;
        g_s2[row] = ss;
    }
}

// ---------------------------------------------------------------------------
// Main fused kernel: 128x128 tile of dot products -> sim -> exp ->
// row/col partial sums + diagonal sim.
// ---------------------------------------------------------------------------
#define BM 128
#define BN 128
#define BK 32
#define SMEM_STRIDE 132   // 128 + 4 pad: conflict-free transposed STS, 16B-aligned rows

__global__ __launch_bounds__(256, 2)
void dcl_main_kernel(const float* __restrict__ C,
                     const float* __restrict__ S,
                     const float* __restrict__ T) {
    __shared__ float As[BK][SMEM_STRIDE];
    __shared__ float Bs[BK][SMEM_STRIDE];
    __shared__ float colP[BN];

    const int tid = threadIdx.x;
    const int tx  = tid & 15;   // 0..15 -> column group
    const int ty  = tid >> 4;   // 0..15 -> row group
    const int rowBase = blockIdx.y * BM;
    const int colBase = blockIdx.x * BN;

    float acc[8][8];
#pragma unroll
    for (int i = 0; i < 8; i++)
#pragma unroll
        for (int j = 0; j < 8; j++) acc[i][j] = 0.0f;

    for (int k0 = 0; k0 < DIM; k0 += BK) {
        __syncthreads();  // previous compute done before overwriting tiles
#pragma unroll
        for (int t = 0; t < 4; t++) {
            int idx = tid + t * 256;
            int r   = idx >> 3;     // 0..127
            int kg  = idx & 7;      // 0..7 (float4 group within BK)
            float4 va = *(const float4*)(C + (size_t)(rowBase + r) * DIM + k0 + kg * 4);
            As[kg * 4 + 0][r] = va.x;
            As[kg * 4 + 1][r] = va.y;
            As[kg * 4 + 2][r] = va.z;
            As[kg * 4 + 3][r] = va.w;
            float4 vb = *(const float4*)(S + (size_t)(colBase + r) * DIM + k0 + kg * 4);
            Bs[kg * 4 + 0][r] = vb.x;
            Bs[kg * 4 + 1][r] = vb.y;
            Bs[kg * 4 + 2][r] = vb.z;
            Bs[kg * 4 + 3][r] = vb.w;
        }
        __syncthreads();

#pragma unroll
        for (int k = 0; k < BK; k++) {
            float a[8], b[8];
            *(float4*)(a + 0) = *(const float4*)&As[k][ty * 8 + 0];
            *(float4*)(a + 4) = *(const float4*)&As[k][ty * 8 + 4];
            *(float4*)(b + 0) = *(const float4*)&Bs[k][tx * 8 + 0];
            *(float4*)(b + 4) = *(const float4*)&Bs[k][tx * 8 + 4];
#pragma unroll
            for (int i = 0; i < 8; i++)
#pragma unroll
                for (int j = 0; j < 8; j++)
                    acc[i][j] = fmaf(a[i], b[j], acc[i][j]);
        }
    }

    // ---------------- epilogue ----------------
    const float expT = __expf(T[0]);

    float c2r[8], s2c[8];
#pragma unroll
    for (int i = 0; i < 8; i++) c2r[i] = g_c2[rowBase + ty * 8 + i];
#pragma unroll
    for (int j = 0; j < 8; j++) s2c[j] = g_s2[colBase + tx * 8 + j];

    float rAcc[8], cAcc[8];
#pragma unroll
    for (int i = 0; i < 8; i++) { rAcc[i] = 0.0f; cAcc[i] = 0.0f; }
    float dloc = 0.0f;

#pragma unroll
    for (int i = 0; i < 8; i++) {
#pragma unroll
        for (int j = 0; j < 8; j++) {
            float d2   = c2r[i] + s2c[j] - 2.0f * acc[i][j];
            float dist = sqrtf(fmaxf(d2, 0.0f));
            float sim  = -dist * expT;
            float e    = __expf(sim);
            rAcc[i] += e;
            cAcc[j] += e;
            if (rowBase + ty * 8 + i == colBase + tx * 8 + j) dloc += sim;
        }
    }

    // row sums: reduce across tx (lane bits 0..3), then one atomic per row
#pragma unroll
    for (int i = 0; i < 8; i++) {
        float v = rAcc[i];
        v += __shfl_xor_sync(0xffffffffu, v, 1);
        v += __shfl_xor_sync(0xffffffffu, v, 2);
        v += __shfl_xor_sync(0xffffffffu, v, 4);
        v += __shfl_xor_sync(0xffffffffu, v, 8);
        if (tx == 0) atomicAdd(&g_rowsum[rowBase + ty * 8 + i], v);
    }

    // col sums: smem reduction, then one atomic per column
    __syncthreads();
    if (tid < BN) colP[tid] = 0.0f;
    __syncthreads();
#pragma unroll
    for (int j = 0; j < 8; j++) atomicAdd(&colP[tx * 8 + j], cAcc[j]);
    __syncthreads();
    if (tid < BN) atomicAdd(&g_colsum[colBase + tid], colP[tid]);

    // diagonal sim sum (only diagonal CTAs contribute)
    if (blockIdx.x == blockIdx.y) {
        dloc += __shfl_xor_sync(0xffffffffu, dloc, 1);
        dloc += __shfl_xor_sync(0xffffffffu, dloc, 2);
        dloc += __shfl_xor_sync(0xffffffffu, dloc, 4);
        dloc += __shfl_xor_sync(0xffffffffu, dloc, 8);
        dloc += __shfl_xor_sync(0xffffffffu, dloc, 16);
        if ((tid & 31) == 0) atomicAdd(&g_diag, dloc);
    }
}

// ---------------------------------------------------------------------------
// Final: loss = (0.5 * sum_i(log rowsum_i + log colsum_i) - sum_i sim_ii) / N
// ---------------------------------------------------------------------------
__global__ void dcl_final_kernel(float* __restrict__ out) {
    __shared__ float red[256];
    float acc = 0.0f;
    for (int i = threadIdx.x; i < NPTS; i += 256)
        acc += logf(g_rowsum[i]) + logf(g_colsum[i]);
    red[threadIdx.x] = acc;
    __syncthreads();
    for (int s = 128; s >= 1; s >>= 1) {
        if (threadIdx.x < s) red[threadIdx.x] += red[threadIdx.x + s];
        __syncthreads();
    }
    if (threadIdx.x == 0)
        out[0] = (0.5f * red[0] - g_diag) / (float)NPTS;
}

// ---------------------------------------------------------------------------
extern "C" void kernel_launch(void* const* d_in, const int* in_sizes, int n_in,
                              void* d_out, int out_size) {
    const float* C = (const float*)d_in[0];  // cond_feature [8192, 256]
    const float* S = (const float*)d_in[1];  // sol_feature  [8192, 256]
    const float* T = (const float*)d_in[2];  // temperature scalar
    float* out = (float*)d_out;

    dcl_init_kernel<<<(NPTS + 255) / 256, 256>>>();
    dcl_norms_kernel<<<NPTS / 8, 256>>>(C, S);
    dim3 grid(NPTS / BN, NPTS / BM);
    dcl_main_kernel<<<grid, 256>>>(C, S, T);
    dcl_final_kernel<<<1, 256>>>(out);
}

// round 2
// speedup vs baseline: 1.8411x; 1.8411x over previous
#include <cuda_runtime.h>
#include <math.h>

#define NPTS 8192
#define DIM  256

__device__ float g_c2[NPTS];
__device__ float g_s2[NPTS];
__device__ float g_rowsum[NPTS];
__device__ float g_colsum[NPTS];
__device__ float g_diag;

// ---------------------------------------------------------------------------
__global__ void dcl_init_kernel() {
    int i = blockIdx.x * blockDim.x + threadIdx.x;
    if (i < NPTS) {
        g_rowsum[i] = 0.0f;
        g_colsum[i] = 0.0f;
    }
    if (i == 0) g_diag = 0.0f;
}

// ---------------------------------------------------------------------------
// Row norms in full fp32 (precision anchor for d2 = c2 + s2 - 2*dot)
// ---------------------------------------------------------------------------
__global__ void dcl_norms_kernel(const float* __restrict__ C,
                                 const float* __restrict__ S) {
    int warp = threadIdx.x >> 5;
    int lane = threadIdx.x & 31;
    int row  = blockIdx.x * 8 + warp;

    const float4* c4 = (const float4*)(C + (size_t)row * DIM);
    const float4* s4 = (const float4*)(S + (size_t)row * DIM);

    float cs = 0.0f, ss = 0.0f;
#pragma unroll
    for (int t = 0; t < 2; t++) {
        float4 v = c4[lane + t * 32];
        cs += v.x * v.x + v.y * v.y + v.z * v.z + v.w * v.w;
        float4 w = s4[lane + t * 32];
        ss += w.x * w.x + w.y * w.y + w.z * w.z + w.w * w.w;
    }
#pragma unroll
    for (int m = 16; m >= 1; m >>= 1) {
        cs += __shfl_xor_sync(0xffffffffu, cs, m);
        ss += __shfl_xor_sync(0xffffffffu, ss, m);
    }
    if (lane == 0) {
        g_c2[row] = cs;
        g_s2[row] = ss;
    }
}

// ---------------------------------------------------------------------------
// tf32 helpers
// ---------------------------------------------------------------------------
__device__ __forceinline__ float f2tf32(float x) {
    unsigned u;
    asm("cvt.rna.tf32.f32 %0, %1;" : "=r"(u) : "f"(x));
    return __uint_as_float(u);
}

__device__ __forceinline__ void mma_tf32(float* d, const unsigned* a, const unsigned* b) {
    asm volatile(
        "mma.sync.aligned.m16n8k8.row.col.f32.tf32.tf32.f32 "
        "{%0,%1,%2,%3}, {%4,%5,%6,%7}, {%8,%9}, {%0,%1,%2,%3};\n"
        : "+f"(d[0]), "+f"(d[1]), "+f"(d[2]), "+f"(d[3])
        : "r"(a[0]), "r"(a[1]), "r"(a[2]), "r"(a[3]), "r"(b[0]), "r"(b[1]));
}

// ---------------------------------------------------------------------------
// Main fused kernel: tf32 tensor-core GEMM tile 128x128 + distance/exp epilogue
// ---------------------------------------------------------------------------
#define BM 128
#define BN 128
#define BK 32
#define KPAD 36          // 32 + 4 floats pad: conflict-free STS.128 + frag LDS

#define LOG2E 1.4426950408889634f

__global__ __launch_bounds__(256, 2)
void dcl_main_kernel(const float* __restrict__ C,
                     const float* __restrict__ S,
                     const float* __restrict__ T) {
    __shared__ float As[BM][KPAD];   // row-major [m][k]
    __shared__ float Bs[BN][KPAD];   // row-major [n][k]

    const int tid  = threadIdx.x;
    const int lane = tid & 31;
    const int warp = tid >> 5;
    const int warpM = warp & 1;      // 2 warps along M  (64 rows each)
    const int warpN = warp >> 1;     // 4 warps along N  (32 cols each)
    const int g   = lane >> 2;       // 0..7
    const int tig = lane & 3;        // 0..3

    const int rowBase = blockIdx.y * BM;
    const int colBase = blockIdx.x * BN;

    float acc[4][4][4];
#pragma unroll
    for (int mi = 0; mi < 4; mi++)
#pragma unroll
        for (int ni = 0; ni < 4; ni++)
#pragma unroll
            for (int c = 0; c < 4; c++) acc[mi][ni][c] = 0.0f;

    for (int k0 = 0; k0 < DIM; k0 += BK) {
        __syncthreads();
#pragma unroll
        for (int t = 0; t < 4; t++) {
            int idx = tid + t * 256;
            int r   = idx >> 3;     // 0..127
            int kg  = idx & 7;      // float4 group within BK
            float4 va = *(const float4*)(C + (size_t)(rowBase + r) * DIM + k0 + kg * 4);
            va.x = f2tf32(va.x); va.y = f2tf32(va.y);
            va.z = f2tf32(va.z); va.w = f2tf32(va.w);
            *(float4*)&As[r][kg * 4] = va;
            float4 vb = *(const float4*)(S + (size_t)(colBase + r) * DIM + k0 + kg * 4);
            vb.x = f2tf32(vb.x); vb.y = f2tf32(vb.y);
            vb.z = f2tf32(vb.z); vb.w = f2tf32(vb.w);
            *(float4*)&Bs[r][kg * 4] = vb;
        }
        __syncthreads();

#pragma unroll
        for (int kk = 0; kk < 4; kk++) {
            const int kb = kk * 8 + tig;
            unsigned a[4][4], b[4][2];
#pragma unroll
            for (int mi = 0; mi < 4; mi++) {
                const int m0 = warpM * 64 + mi * 16 + g;
                a[mi][0] = __float_as_uint(As[m0][kb]);
                a[mi][1] = __float_as_uint(As[m0 + 8][kb]);
                a[mi][2] = __float_as_uint(As[m0][kb + 4]);
                a[mi][3] = __float_as_uint(As[m0 + 8][kb + 4]);
            }
#pragma unroll
            for (int ni = 0; ni < 4; ni++) {
                const int n0 = warpN * 32 + ni * 8 + g;
                b[ni][0] = __float_as_uint(Bs[n0][kb]);
                b[ni][1] = __float_as_uint(Bs[n0][kb + 4]);
            }
#pragma unroll
            for (int mi = 0; mi < 4; mi++)
#pragma unroll
                for (int ni = 0; ni < 4; ni++)
                    mma_tf32(acc[mi][ni], a[mi], b[ni]);
        }
    }

    // ---------------- epilogue ----------------
    __syncthreads();   // done reading As/Bs; reuse the smem

    float* rowP = &As[0][0];         // [128]
    float* colP = rowP + 128;        // [128]
    float* c2s  = rowP + 256;        // [128]
    float* s2s  = rowP + 384;        // [128]

    if (tid < 128) {
        rowP[tid] = 0.0f;
        colP[tid] = 0.0f;
        c2s[tid] = g_c2[rowBase + tid];
        s2s[tid] = g_s2[colBase + tid];
    }
    __syncthreads();

    const float negExpT = -__expf(T[0]);
    const bool diagCTA = (blockIdx.x == blockIdx.y);

    float rAcc[8], cAcc[8];
#pragma unroll
    for (int i = 0; i < 8; i++) { rAcc[i] = 0.0f; cAcc[i] = 0.0f; }
    float dloc = 0.0f;

#pragma unroll
    for (int mi = 0; mi < 4; mi++) {
#pragma unroll
        for (int ni = 0; ni < 4; ni++) {
#pragma unroll
            for (int c = 0; c < 4; c++) {
                const int h  = c >> 1;                       // +8 row half
                const int bb = c & 1;                        // +1 col
                const int rl = warpM * 64 + mi * 16 + g + h * 8;
                const int cl = warpN * 32 + ni * 8 + tig * 2 + bb;
                float d2   = c2s[rl] + s2s[cl] - 2.0f * acc[mi][ni][c];
                float dist = sqrtf(fmaxf(d2, 0.0f));
                float sim  = dist * negExpT;
                float e    = exp2f(sim * LOG2E);
                rAcc[mi * 2 + h] += e;
                cAcc[ni * 2 + bb] += e;
                if (diagCTA && rl == cl) dloc += sim;
            }
        }
    }

    // row sums: reduce over tig (columns of the warp), leader atomics to smem
#pragma unroll
    for (int i = 0; i < 8; i++) {
        float v = rAcc[i];
        v += __shfl_xor_sync(0xffffffffu, v, 1);
        v += __shfl_xor_sync(0xffffffffu, v, 2);
        if (tig == 0) {
            int mi = i >> 1, h = i & 1;
            atomicAdd(&rowP[warpM * 64 + mi * 16 + h * 8 + g], v);
        }
    }
    // col sums: reduce over g (rows of the warp)
#pragma unroll
    for (int i = 0; i < 8; i++) {
        float v = cAcc[i];
        v += __shfl_xor_sync(0xffffffffu, v, 4);
        v += __shfl_xor_sync(0xffffffffu, v, 8);
        v += __shfl_xor_sync(0xffffffffu, v, 16);
        if (g == 0) {
            int ni = i >> 1, bb = i & 1;
            atomicAdd(&colP[warpN * 32 + ni * 8 + tig * 2 + bb], v);
        }
    }

    if (diagCTA) {
#pragma unroll
        for (int m = 16; m >= 1; m >>= 1)
            dloc += __shfl_xor_sync(0xffffffffu, dloc, m);
        if (lane == 0) atomicAdd(&g_diag, dloc);
    }

    __syncthreads();
    if (tid < 128) {
        atomicAdd(&g_rowsum[rowBase + tid], rowP[tid]);
        atomicAdd(&g_colsum[colBase + tid], colP[tid]);
    }
}

// ---------------------------------------------------------------------------
__global__ void dcl_final_kernel(float* __restrict__ out) {
    __shared__ float red[1024];
    float acc = 0.0f;
    for (int i = threadIdx.x; i < NPTS; i += 1024)
        acc += logf(g_rowsum[i]) + logf(g_colsum[i]);
    red[threadIdx.x] = acc;
    __syncthreads();
    for (int s = 512; s >= 1; s >>= 1) {
        if (threadIdx.x < s) red[threadIdx.x] += red[threadIdx.x + s];
        __syncthreads();
    }
    if (threadIdx.x == 0)
        out[0] = (0.5f * red[0] - g_diag) / (float)NPTS;
}

// ---------------------------------------------------------------------------
extern "C" void kernel_launch(void* const* d_in, const int* in_sizes, int n_in,
                              void* d_out, int out_size) {
    const float* C = (const float*)d_in[0];  // cond_feature [8192, 256]
    const float* S = (const float*)d_in[1];  // sol_feature  [8192, 256]
    const float* T = (const float*)d_in[2];  // temperature scalar
    float* out = (float*)d_out;

    dcl_init_kernel<<<(NPTS + 255) / 256, 256>>>();
    dcl_norms_kernel<<<NPTS / 8, 256>>>(C, S);
    dim3 grid(NPTS / BN, NPTS / BM);
    dcl_main_kernel<<<grid, 256>>>(C, S, T);
    dcl_final_kernel<<<1, 1024>>>(out);
}

// round 5
// speedup vs baseline: 3.7087x; 2.0144x over previous
#include <cuda_runtime.h>
#include <cuda_bf16.h>
#include <math.h>
#include <stdint.h>

#define NPTS 8192
#define DIM  256
#define BM 128
#define BN 128
#define BKC 64            // k-columns per chunk (bf16), 128B rows
#define NCHUNK 4          // 256 / 64

// dynamic smem layout (bytes): two A buffers (16KB), two B buffers (16KB), aux
#define OFF_A0 0
#define OFF_A1 16384
#define OFF_B0 32768
#define OFF_B1 49152
#define OFF_AUX 65536     // c2s[128], s2s[128], rowP[128], colP[128]
#define SMEM_TOTAL (65536 + 2048)

static __device__ float g_c2[NPTS], g_s2[NPTS];
static __device__ float g_rowsum[NPTS], g_colsum[NPTS];
static __device__ float g_diag, g_logsum;

// ---------------------------------------------------------------------------
__device__ __forceinline__ uint32_t smem_u32(const void* p) {
    uint32_t a;
    asm("{.reg .u64 t; cvta.to.shared.u64 t, %1; cvt.u32.u64 %0, t;}" : "=r"(a) : "l"(p));
    return a;
}
__device__ __forceinline__ uint32_t swz(uint32_t x) { return x ^ ((x >> 3) & 0x70); }

__device__ __forceinline__ void sts128(uint32_t a, uint32_t x, uint32_t y,
                                       uint32_t z, uint32_t w) {
    asm volatile("st.shared.v4.b32 [%0], {%1,%2,%3,%4};" :: "r"(a), "r"(x), "r"(y), "r"(z), "r"(w));
}
__device__ __forceinline__ void ldsm4(uint32_t* r, uint32_t a) {
    asm volatile("ldmatrix.sync.aligned.m8n8.x4.shared.b16 {%0,%1,%2,%3}, [%4];"
                 : "=r"(r[0]), "=r"(r[1]), "=r"(r[2]), "=r"(r[3]) : "r"(a));
}
__device__ __forceinline__ void mma_bf16(float* d, const uint32_t* a, const uint32_t* b) {
    asm volatile(
        "mma.sync.aligned.m16n8k16.row.col.f32.bf16.bf16.f32 "
        "{%0,%1,%2,%3}, {%4,%5,%6,%7}, {%8,%9}, {%0,%1,%2,%3};\n"
        : "+f"(d[0]), "+f"(d[1]), "+f"(d[2]), "+f"(d[3])
        : "r"(a[0]), "r"(a[1]), "r"(a[2]), "r"(a[3]), "r"(b[0]), "r"(b[1]));
}
__device__ __forceinline__ uint32_t packbf(float lo, float hi) {
    __nv_bfloat162 p = __float22bfloat162_rn(make_float2(lo, hi));
    return *(uint32_t*)&p;
}
__device__ __forceinline__ float rbf(float x) {
    return __bfloat162float(__float2bfloat16_rn(x));
}

// ---------------------------------------------------------------------------
// Norms from bf16-rounded inputs (consistent with the MMA operands) + zero accums
// ---------------------------------------------------------------------------
__global__ void dcl_norms_kernel(const float* __restrict__ C,
                                 const float* __restrict__ S) {
    int warp = threadIdx.x >> 5;
    int lane = threadIdx.x & 31;
    int row  = blockIdx.x * 8 + warp;

    if (threadIdx.x < 8) {
        int zr = blockIdx.x * 8 + threadIdx.x;
        g_rowsum[zr] = 0.0f;
        g_colsum[zr] = 0.0f;
    }
    if (blockIdx.x == 0 && threadIdx.x == 0) { g_diag = 0.0f; g_logsum = 0.0f; }

    const float4* c4 = (const float4*)(C + (size_t)row * DIM);
    const float4* s4 = (const float4*)(S + (size_t)row * DIM);
    float cs = 0.0f, ss = 0.0f;
#pragma unroll
    for (int t = 0; t < 2; t++) {
        float4 v = c4[lane + t * 32];
        float x = rbf(v.x), y = rbf(v.y), z = rbf(v.z), w = rbf(v.w);
        cs += x * x + y * y + z * z + w * w;
        float4 u = s4[lane + t * 32];
        x = rbf(u.x); y = rbf(u.y); z = rbf(u.z); w = rbf(u.w);
        ss += x * x + y * y + z * z + w * w;
    }
#pragma unroll
    for (int m = 16; m >= 1; m >>= 1) {
        cs += __shfl_xor_sync(0xffffffffu, cs, m);
        ss += __shfl_xor_sync(0xffffffffu, ss, m);
    }
    if (lane == 0) { g_c2[row] = cs; g_s2[row] = ss; }
}

// ---------------------------------------------------------------------------
// Main: bf16 m16n8k16 mma.sync GEMM (128x128 tile) + fused distance epilogue
// ---------------------------------------------------------------------------
__global__ __launch_bounds__(256, 2)
void dcl_main_kernel(const float* __restrict__ C,
                     const float* __restrict__ S,
                     const float* __restrict__ T) {
    extern __shared__ char smem[];
    const uint32_t sb = smem_u32(smem);

    const int tid   = threadIdx.x;
    const int lane  = tid & 31;
    const int warp  = tid >> 5;
    const int warpM = warp & 1;        // 2 warps along M (64 rows)
    const int warpN = warp >> 1;       // 4 warps along N (32 cols)
    const int rowBase = blockIdx.y * BM;
    const int colBase = blockIdx.x * BN;

    // ldmatrix lane decomposition
    const int mrow  = lane & 7;
    const int matLo = (lane >> 3) & 1;
    const int matHi = (lane >> 4) & 1;

    float* aux  = (float*)(smem + OFF_AUX);
    float* c2s  = aux;
    float* s2s  = aux + 128;
    float* rowP = aux + 256;
    float* colP = aux + 384;
    if (tid < 128) {
        c2s[tid] = g_c2[rowBase + tid];
        s2s[tid] = g_s2[colBase + tid];
        rowP[tid] = 0.0f;
        colP[tid] = 0.0f;
    }

    const uint32_t aB[2] = { sb + OFF_A0, sb + OFF_A1 };
    const uint32_t bB[2] = { sb + OFF_B0, sb + OFF_B1 };

    float acc[4][4][4];
#pragma unroll
    for (int mi = 0; mi < 4; mi++)
#pragma unroll
        for (int ni = 0; ni < 4; ni++)
#pragma unroll
            for (int c = 0; c < 4; c++) acc[mi][ni][c] = 0.0f;

    auto fill = [&](int buf, int ch) {
        const float* cg = C + (size_t)rowBase * DIM + ch * BKC;
        const float* sg = S + (size_t)colBase * DIM + ch * BKC;
#pragma unroll
        for (int t = 0; t < 4; t++) {
            int idx = tid + t * 256;
            int r = idx >> 3, g = idx & 7;
            const float4* p = (const float4*)(cg + (size_t)r * DIM + g * 8);
            float4 v0 = p[0], v1 = p[1];
            sts128(aB[buf] + swz((uint32_t)(r * 128 + g * 16)),
                   packbf(v0.x, v0.y), packbf(v0.z, v0.w),
                   packbf(v1.x, v1.y), packbf(v1.z, v1.w));
        }
#pragma unroll
        for (int t = 0; t < 4; t++) {
            int idx = tid + t * 256;
            int r = idx >> 3, g = idx & 7;
            const float4* p = (const float4*)(sg + (size_t)r * DIM + g * 8);
            float4 v0 = p[0], v1 = p[1];
            sts128(bB[buf] + swz((uint32_t)(r * 128 + g * 16)),
                   packbf(v0.x, v0.y), packbf(v0.z, v0.w),
                   packbf(v1.x, v1.y), packbf(v1.z, v1.w));
        }
    };

    fill(0, 0);

    // per-lane ldmatrix base addresses (byte offsets into a buffer)
    const uint32_t aRowOff = (uint32_t)(warpM * 64 + matLo * 8 + mrow) * 128;
    const uint32_t bRowOff = (uint32_t)(warpN * 32 + matHi * 8 + mrow) * 128;

#pragma unroll
    for (int ch = 0; ch < NCHUNK; ch++) {
        __syncthreads();
        if (ch + 1 < NCHUNK) fill((ch + 1) & 1, ch + 1);
        const uint32_t ab = aB[ch & 1] + aRowOff;
        const uint32_t bb = bB[ch & 1] + bRowOff;

#pragma unroll
        for (int ks = 0; ks < 4; ks++) {
            const uint32_t ca = (uint32_t)((((ks << 1) | matHi) ^ mrow) << 4);
            const uint32_t cb = (uint32_t)((((ks << 1) | matLo) ^ mrow) << 4);
            uint32_t a[4][4], b[4][2];
#pragma unroll
            for (int mi = 0; mi < 4; mi++)
                ldsm4(a[mi], ab + mi * 2048 + ca);
#pragma unroll
            for (int p = 0; p < 2; p++) {
                uint32_t r[4];
                ldsm4(r, bb + p * 2048 + cb);
                b[2 * p][0] = r[0]; b[2 * p][1] = r[1];
                b[2 * p + 1][0] = r[2]; b[2 * p + 1][1] = r[3];
            }
#pragma unroll
            for (int mi = 0; mi < 4; mi++)
#pragma unroll
                for (int ni = 0; ni < 4; ni++)
                    mma_bf16(acc[mi][ni], a[mi], b[ni]);
        }
    }

    // ---------------- epilogue ----------------
    __syncthreads();

    const float negExpT = -__expf(T[0]);
    const bool diagCTA = (blockIdx.x == blockIdx.y);
    const int g   = lane >> 2;
    const int tig = lane & 3;

    float rAcc[8], cAcc[8];
#pragma unroll
    for (int i = 0; i < 8; i++) { rAcc[i] = 0.0f; cAcc[i] = 0.0f; }
    float dloc = 0.0f;

#pragma unroll
    for (int mi = 0; mi < 4; mi++) {
#pragma unroll
        for (int ni = 0; ni < 4; ni++) {
#pragma unroll
            for (int c = 0; c < 4; c++) {
                const int h  = c >> 1;
                const int bb2 = c & 1;
                const int rl = warpM * 64 + mi * 16 + g + h * 8;
                const int cl = warpN * 32 + ni * 8 + tig * 2 + bb2;
                float d2   = c2s[rl] + s2s[cl] - 2.0f * acc[mi][ni][c];
                float dist;
                asm("sqrt.approx.f32 %0, %1;" : "=f"(dist) : "f"(fmaxf(d2, 0.0f)));
                float simv = dist * negExpT;
                float e    = __expf(simv);
                rAcc[mi * 2 + h] += e;
                cAcc[ni * 2 + bb2] += e;
                if (diagCTA && rl == cl) dloc += simv;
            }
        }
    }

#pragma unroll
    for (int i = 0; i < 8; i++) {
        float v = rAcc[i];
        v += __shfl_xor_sync(0xffffffffu, v, 1);
        v += __shfl_xor_sync(0xffffffffu, v, 2);
        if (tig == 0) {
            int mi = i >> 1, h = i & 1;
            atomicAdd(&rowP[warpM * 64 + mi * 16 + h * 8 + g], v);
        }
    }
#pragma unroll
    for (int i = 0; i < 8; i++) {
        float v = cAcc[i];
        v += __shfl_xor_sync(0xffffffffu, v, 4);
        v += __shfl_xor_sync(0xffffffffu, v, 8);
        v += __shfl_xor_sync(0xffffffffu, v, 16);
        if (g == 0) {
            int ni = i >> 1, bb2 = i & 1;
            atomicAdd(&colP[warpN * 32 + ni * 8 + tig * 2 + bb2], v);
        }
    }

    if (diagCTA) {
#pragma unroll
        for (int m = 16; m >= 1; m >>= 1)
            dloc += __shfl_xor_sync(0xffffffffu, dloc, m);
        if (lane == 0) atomicAdd(&g_diag, dloc);
    }

    __syncthreads();
    if (tid < 128) {
        atomicAdd(&g_rowsum[rowBase + tid], rowP[tid]);
        atomicAdd(&g_colsum[colBase + tid], colP[tid]);
    }
}

// ---------------------------------------------------------------------------
__global__ void dcl_final1_kernel() {
    int i = blockIdx.x * blockDim.x + threadIdx.x;
    float v = logf(g_rowsum[i]) + logf(g_colsum[i]);
#pragma unroll
    for (int m = 16; m >= 1; m >>= 1) v += __shfl_xor_sync(0xffffffffu, v, m);
    if ((threadIdx.x & 31) == 0) atomicAdd(&g_logsum, v);
}

__global__ void dcl_final2_kernel(float* __restrict__ out) {
    out[0] = (0.5f * g_logsum - g_diag) / (float)NPTS;
}

// ---------------------------------------------------------------------------
extern "C" void kernel_launch(void* const* d_in, const int* in_sizes, int n_in,
                              void* d_out, int out_size) {
    const float* C = (const float*)d_in[0];
    const float* S = (const float*)d_in[1];
    const float* T = (const float*)d_in[2];
    float* out = (float*)d_out;

    static bool attr_set = false;
    if (!attr_set) {
        cudaFuncSetAttribute(dcl_main_kernel,
                             cudaFuncAttributeMaxDynamicSharedMemorySize, SMEM_TOTAL);
        attr_set = true;
    }

    dcl_norms_kernel<<<NPTS / 8, 256>>>(C, S);
    dim3 grid(NPTS / BN, NPTS / BM);
    dcl_main_kernel<<<grid, 256, SMEM_TOTAL>>>(C, S, T);
    dcl_final1_kernel<<<NPTS / 1024, 1024>>>();
    dcl_final2_kernel<<<1, 1>>>(out);
}

// round 6
// speedup vs baseline: 6.6715x; 1.7989x over previous
#include <cuda_runtime.h>
#include <cuda_bf16.h>
#include <math.h>
#include <stdint.h>

#define NPTS 8192
#define DIM  256
#define BM 128
#define BN 128
#define BKC 64            // k-columns per chunk (bf16), 128B rows
#define NCHUNK 4          // 256 / 64

// dynamic smem (bytes): A0,A1,B0,B1 (16KB each) + aux
#define OFF_A0 0
#define OFF_A1 16384
#define OFF_B0 32768
#define OFF_B1 49152
#define OFF_AUX 65536     // c2s[128], s2s[128], rowP[128], colP[128]
#define SMEM_TOTAL (65536 + 2048)

static __device__ __nv_bfloat16 g_Cb[NPTS * DIM];
static __device__ __nv_bfloat16 g_Sb[NPTS * DIM];
static __device__ float g_c2[NPTS], g_s2[NPTS];
static __device__ float g_rowsum[NPTS], g_colsum[NPTS];

// ---------------------------------------------------------------------------
__device__ __forceinline__ uint32_t smem_u32(const void* p) {
    uint32_t a;
    asm("{.reg .u64 t; cvta.to.shared.u64 t, %1; cvt.u32.u64 %0, t;}" : "=r"(a) : "l"(p));
    return a;
}
__device__ __forceinline__ uint32_t swz(uint32_t x) { return x ^ ((x >> 3) & 0x70); }

__device__ __forceinline__ void cp16(uint32_t dst, const void* src) {
    asm volatile("cp.async.cg.shared.global [%0], [%1], 16;" :: "r"(dst), "l"(src));
}
__device__ __forceinline__ void ldsm4(uint32_t* r, uint32_t a) {
    asm volatile("ldmatrix.sync.aligned.m8n8.x4.shared.b16 {%0,%1,%2,%3}, [%4];"
                 : "=r"(r[0]), "=r"(r[1]), "=r"(r[2]), "=r"(r[3]) : "r"(a));
}
__device__ __forceinline__ void mma_bf16(float* d, const uint32_t* a, const uint32_t* b) {
    asm volatile(
        "mma.sync.aligned.m16n8k16.row.col.f32.bf16.bf16.f32 "
        "{%0,%1,%2,%3}, {%4,%5,%6,%7}, {%8,%9}, {%0,%1,%2,%3};\n"
        : "+f"(d[0]), "+f"(d[1]), "+f"(d[2]), "+f"(d[3])
        : "r"(a[0]), "r"(a[1]), "r"(a[2]), "r"(a[3]), "r"(b[0]), "r"(b[1]));
}
__device__ __forceinline__ uint32_t packbf(float lo, float hi) {
    __nv_bfloat162 p = __float22bfloat162_rn(make_float2(lo, hi));
    return *(uint32_t*)&p;
}
__device__ __forceinline__ float rbf(float x) {
    return __bfloat162float(__float2bfloat16_rn(x));
}

// ---------------------------------------------------------------------------
// Prepass: f32 -> bf16 copies, norms from rounded values, zero accumulators.
// One warp per row; handles C and S for that row. grid = NPTS/8, block = 256.
// ---------------------------------------------------------------------------
__global__ void dcl_prep_kernel(const float* __restrict__ C,
                                const float* __restrict__ S,
                                float* __restrict__ out) {
    int warp = threadIdx.x >> 5;
    int lane = threadIdx.x & 31;
    int row  = blockIdx.x * 8 + warp;

    if (lane == 0) { g_rowsum[row] = 0.0f; g_colsum[row] = 0.0f; }
    if (blockIdx.x == 0 && threadIdx.x == 0) out[0] = 0.0f;

    // C
    {
        const float4* src = (const float4*)(C + (size_t)row * DIM);
        float4 v0 = src[lane * 2], v1 = src[lane * 2 + 1];
        float a = rbf(v0.x), b = rbf(v0.y), c = rbf(v0.z), d = rbf(v0.w);
        float e = rbf(v1.x), f = rbf(v1.y), g = rbf(v1.z), h = rbf(v1.w);
        float ss = a * a + b * b + c * c + d * d + e * e + f * f + g * g + h * h;
        uint4 pk = make_uint4(packbf(v0.x, v0.y), packbf(v0.z, v0.w),
                              packbf(v1.x, v1.y), packbf(v1.z, v1.w));
        ((uint4*)(g_Cb + (size_t)row * DIM))[lane] = pk;
#pragma unroll
        for (int m = 16; m >= 1; m >>= 1) ss += __shfl_xor_sync(0xffffffffu, ss, m);
        if (lane == 0) g_c2[row] = ss;
    }
    // S
    {
        const float4* src = (const float4*)(S + (size_t)row * DIM);
        float4 v0 = src[lane * 2], v1 = src[lane * 2 + 1];
        float a = rbf(v0.x), b = rbf(v0.y), c = rbf(v0.z), d = rbf(v0.w);
        float e = rbf(v1.x), f = rbf(v1.y), g = rbf(v1.z), h = rbf(v1.w);
        float ss = a * a + b * b + c * c + d * d + e * e + f * f + g * g + h * h;
        uint4 pk = make_uint4(packbf(v0.x, v0.y), packbf(v0.z, v0.w),
                              packbf(v1.x, v1.y), packbf(v1.z, v1.w));
        ((uint4*)(g_Sb + (size_t)row * DIM))[lane] = pk;
#pragma unroll
        for (int m = 16; m >= 1; m >>= 1) ss += __shfl_xor_sync(0xffffffffu, ss, m);
        if (lane == 0) g_s2[row] = ss;
    }
}

// ---------------------------------------------------------------------------
// Main: bf16 m16n8k16 GEMM (128x128 tile) via cp.async pipeline + fused epilogue
// ---------------------------------------------------------------------------
__global__ __launch_bounds__(256, 2)
void dcl_main_kernel(const float* __restrict__ T, float* __restrict__ out) {
    extern __shared__ char smem[];
    const uint32_t sb = smem_u32(smem);

    const int tid   = threadIdx.x;
    const int lane  = tid & 31;
    const int warp  = tid >> 5;
    const int warpM = warp & 1;        // 2 warps along M (64 rows)
    const int warpN = warp >> 1;       // 4 warps along N (32 cols)
    const int rowBase = blockIdx.y * BM;
    const int colBase = blockIdx.x * BN;

    const int mrow  = lane & 7;
    const int matLo = (lane >> 3) & 1;
    const int matHi = (lane >> 4) & 1;

    float* aux  = (float*)(smem + OFF_AUX);
    float* c2s  = aux;
    float* s2s  = aux + 128;
    float* rowP = aux + 256;
    float* colP = aux + 384;
    if (tid < 128) {
        c2s[tid] = g_c2[rowBase + tid];
        s2s[tid] = g_s2[colBase + tid];
        rowP[tid] = 0.0f;
        colP[tid] = 0.0f;
    }

    const uint32_t aB[2] = { sb + OFF_A0, sb + OFF_A1 };
    const uint32_t bB[2] = { sb + OFF_B0, sb + OFF_B1 };

    float acc[4][4][4];
#pragma unroll
    for (int mi = 0; mi < 4; mi++)
#pragma unroll
        for (int ni = 0; ni < 4; ni++)
#pragma unroll
            for (int c = 0; c < 4; c++) acc[mi][ni][c] = 0.0f;

    auto fill = [&](int buf, int ch) {
#pragma unroll
        for (int t = 0; t < 4; t++) {
            int idx = tid + t * 256;
            int r = idx >> 3, g = idx & 7;
            cp16(aB[buf] + swz((uint32_t)(r * 128 + g * 16)),
                 g_Cb + (size_t)(rowBase + r) * DIM + ch * BKC + g * 8);
        }
#pragma unroll
        for (int t = 0; t < 4; t++) {
            int idx = tid + t * 256;
            int r = idx >> 3, g = idx & 7;
            cp16(bB[buf] + swz((uint32_t)(r * 128 + g * 16)),
                 g_Sb + (size_t)(colBase + r) * DIM + ch * BKC + g * 8);
        }
        asm volatile("cp.async.commit_group;" ::: "memory");
    };

    fill(0, 0);
    fill(1, 1);

    const uint32_t aRowOff = (uint32_t)(warpM * 64 + matLo * 8 + mrow) * 128;
    const uint32_t bRowOff = (uint32_t)(warpN * 32 + matHi * 8 + mrow) * 128;

#pragma unroll
    for (int ch = 0; ch < NCHUNK; ch++) {
        if (ch < NCHUNK - 1) asm volatile("cp.async.wait_group 1;" ::: "memory");
        else                 asm volatile("cp.async.wait_group 0;" ::: "memory");
        __syncthreads();

        const uint32_t ab = aB[ch & 1] + aRowOff;
        const uint32_t bb = bB[ch & 1] + bRowOff;

#pragma unroll
        for (int ks = 0; ks < 4; ks++) {
            const uint32_t ca = (uint32_t)((((ks << 1) | matHi) ^ mrow) << 4);
            const uint32_t cb = (uint32_t)((((ks << 1) | matLo) ^ mrow) << 4);
            uint32_t a[4][4], b[4][2];
#pragma unroll
            for (int mi = 0; mi < 4; mi++)
                ldsm4(a[mi], ab + mi * 2048 + ca);
#pragma unroll
            for (int p = 0; p < 2; p++) {
                uint32_t r[4];
                ldsm4(r, bb + p * 2048 + cb);
                b[2 * p][0] = r[0]; b[2 * p][1] = r[1];
                b[2 * p + 1][0] = r[2]; b[2 * p + 1][1] = r[3];
            }
#pragma unroll
            for (int mi = 0; mi < 4; mi++)
#pragma unroll
                for (int ni = 0; ni < 4; ni++)
                    mma_bf16(acc[mi][ni], a[mi], b[ni]);
        }

        if (ch + 2 < NCHUNK) {
            __syncthreads();          // all warps done reading buf (ch&1)
            fill(ch & 1, ch + 2);
        }
    }

    // ---------------- epilogue ----------------
    __syncthreads();

    const float negExpT = -__expf(T[0]);
    const bool diagCTA = (blockIdx.x == blockIdx.y);
    const int g   = lane >> 2;
    const int tig = lane & 3;

    float rAcc[8], cAcc[8];
#pragma unroll
    for (int i = 0; i < 8; i++) { rAcc[i] = 0.0f; cAcc[i] = 0.0f; }
    float dloc = 0.0f;

#pragma unroll
    for (int mi = 0; mi < 4; mi++) {
#pragma unroll
        for (int ni = 0; ni < 4; ni++) {
#pragma unroll
            for (int c = 0; c < 4; c++) {
                const int h   = c >> 1;
                const int bb2 = c & 1;
                const int rl = warpM * 64 + mi * 16 + g + h * 8;
                const int cl = warpN * 32 + ni * 8 + tig * 2 + bb2;
                float d2   = c2s[rl] + s2s[cl] - 2.0f * acc[mi][ni][c];
                float dist;
                asm("sqrt.approx.f32 %0, %1;" : "=f"(dist) : "f"(fmaxf(d2, 0.0f)));
                float simv = dist * negExpT;
                float e    = __expf(simv);
                rAcc[mi * 2 + h] += e;
                cAcc[ni * 2 + bb2] += e;
                if (diagCTA && rl == cl) dloc += simv;
            }
        }
    }

#pragma unroll
    for (int i = 0; i < 8; i++) {
        float v = rAcc[i];
        v += __shfl_xor_sync(0xffffffffu, v, 1);
        v += __shfl_xor_sync(0xffffffffu, v, 2);
        if (tig == 0) {
            int mi = i >> 1, h = i & 1;
            atomicAdd(&rowP[warpM * 64 + mi * 16 + h * 8 + g], v);
        }
    }
#pragma unroll
    for (int i = 0; i < 8; i++) {
        float v = cAcc[i];
        v += __shfl_xor_sync(0xffffffffu, v, 4);
        v += __shfl_xor_sync(0xffffffffu, v, 8);
        v += __shfl_xor_sync(0xffffffffu, v, 16);
        if (g == 0) {
            int ni = i >> 1, bb2 = i & 1;
            atomicAdd(&colP[warpN * 32 + ni * 8 + tig * 2 + bb2], v);
        }
    }

    if (diagCTA) {
#pragma unroll
        for (int m = 16; m >= 1; m >>= 1)
            dloc += __shfl_xor_sync(0xffffffffu, dloc, m);
        if (lane == 0) atomicAdd(out, -dloc * (1.0f / (float)NPTS));
    }

    __syncthreads();
    if (tid < 128) {
        atomicAdd(&g_rowsum[rowBase + tid], rowP[tid]);
        atomicAdd(&g_colsum[colBase + tid], colP[tid]);
    }
}

// ---------------------------------------------------------------------------
__global__ void dcl_final_kernel(float* __restrict__ out) {
    int i = blockIdx.x * blockDim.x + threadIdx.x;
    float v = logf(g_rowsum[i]) + logf(g_colsum[i]);
#pragma unroll
    for (int m = 16; m >= 1; m >>= 1) v += __shfl_xor_sync(0xffffffffu, v, m);
    if ((threadIdx.x & 31) == 0)
        atomicAdd(out, v * (0.5f / (float)NPTS));
}

// ---------------------------------------------------------------------------
extern "C" void kernel_launch(void* const* d_in, const int* in_sizes, int n_in,
                              void* d_out, int out_size) {
    const float* C = (const float*)d_in[0];
    const float* S = (const float*)d_in[1];
    const float* T = (const float*)d_in[2];
    float* out = (float*)d_out;

    static bool attr_set = false;
    if (!attr_set) {
        cudaFuncSetAttribute(dcl_main_kernel,
                             cudaFuncAttributeMaxDynamicSharedMemorySize, SMEM_TOTAL);
        attr_set = true;
    }

    dcl_prep_kernel<<<NPTS / 8, 256>>>(C, S, out);
    dim3 grid(NPTS / BN, NPTS / BM);
    dcl_main_kernel<<<grid, 256, SMEM_TOTAL>>>(T, out);
    dcl_final_kernel<<<NPTS / 1024, 1024>>>(out);
}

// round 9
// speedup vs baseline: 6.8900x; 1.0328x over previous
#include <cuda_runtime.h>
#include <cuda_bf16.h>
#include <math.h>
#include <stdint.h>

#define NPTS 8192
#define DIM  256
#define BM 128
#define BN 128
#define BKC 64            // k-columns per chunk (bf16), 128B rows
#define NCHUNK 4          // 256 / 64

// dynamic smem (bytes): A0,A1,B0,B1 (16KB each) + aux
#define OFF_A0 0
#define OFF_A1 16384
#define OFF_B0 32768
#define OFF_B1 49152
#define OFF_AUX 65536     // c2s[128], s2s[128], rowP[128], colP[128]
#define SMEM_TOTAL (65536 + 2048)

#define LN2F 0.6931471805599453f
#define LOG2EF 1.4426950408889634f

static __device__ __nv_bfloat16 g_Cb[NPTS * DIM];
static __device__ __nv_bfloat16 g_Sb[NPTS * DIM];
static __device__ float g_c2[NPTS], g_s2[NPTS];
static __device__ float g_rowsum[NPTS], g_colsum[NPTS];

// ---------------------------------------------------------------------------
__device__ __forceinline__ uint32_t smem_u32(const void* p) {
    uint32_t a;
    asm("{.reg .u64 t; cvta.to.shared.u64 t, %1; cvt.u32.u64 %0, t;}" : "=r"(a) : "l"(p));
    return a;
}
__device__ __forceinline__ uint32_t swz(uint32_t x) { return x ^ ((x >> 3) & 0x70); }

__device__ __forceinline__ void cp16(uint32_t dst, const void* src) {
    asm volatile("cp.async.cg.shared.global [%0], [%1], 16;" :: "r"(dst), "l"(src));
}
__device__ __forceinline__ void ldsm4(uint32_t* r, uint32_t a) {
    asm volatile("ldmatrix.sync.aligned.m8n8.x4.shared.b16 {%0,%1,%2,%3}, [%4];"
                 : "=r"(r[0]), "=r"(r[1]), "=r"(r[2]), "=r"(r[3]) : "r"(a));
}
__device__ __forceinline__ void mma_bf16(float* d, const uint32_t* a, const uint32_t* b) {
    asm volatile(
        "mma.sync.aligned.m16n8k16.row.col.f32.bf16.bf16.f32 "
        "{%0,%1,%2,%3}, {%4,%5,%6,%7}, {%8,%9}, {%0,%1,%2,%3};\n"
        : "+f"(d[0]), "+f"(d[1]), "+f"(d[2]), "+f"(d[3])
        : "r"(a[0]), "r"(a[1]), "r"(a[2]), "r"(a[3]), "r"(b[0]), "r"(b[1]));
}
__device__ __forceinline__ uint32_t packbf(float lo, float hi) {
    __nv_bfloat162 p = __float22bfloat162_rn(make_float2(lo, hi));
    return *(uint32_t*)&p;
}
__device__ __forceinline__ float rbf(float x) {
    return __bfloat162float(__float2bfloat16_rn(x));
}

// ---------------------------------------------------------------------------
// Prepass: f32 -> bf16 copies, norms from rounded values, zero accumulators.
// ---------------------------------------------------------------------------
__global__ void dcl_prep_kernel(const float* __restrict__ C,
                                const float* __restrict__ S,
                                float* __restrict__ out) {
    int warp = threadIdx.x >> 5;
    int lane = threadIdx.x & 31;
    int row  = blockIdx.x * 8 + warp;

    if (lane == 0) { g_rowsum[row] = 0.0f; g_colsum[row] = 0.0f; }
    if (blockIdx.x == 0 && threadIdx.x == 0) out[0] = 0.0f;

    {
        const float4* src = (const float4*)(C + (size_t)row * DIM);
        float4 v0 = src[lane * 2], v1 = src[lane * 2 + 1];
        float a = rbf(v0.x), b = rbf(v0.y), c = rbf(v0.z), d = rbf(v0.w);
        float e = rbf(v1.x), f = rbf(v1.y), g = rbf(v1.z), h = rbf(v1.w);
        float ss = a * a + b * b + c * c + d * d + e * e + f * f + g * g + h * h;
        uint4 pk = make_uint4(packbf(v0.x, v0.y), packbf(v0.z, v0.w),
                              packbf(v1.x, v1.y), packbf(v1.z, v1.w));
        ((uint4*)(g_Cb + (size_t)row * DIM))[lane] = pk;
#pragma unroll
        for (int m = 16; m >= 1; m >>= 1) ss += __shfl_xor_sync(0xffffffffu, ss, m);
        if (lane == 0) g_c2[row] = ss;
    }
    {
        const float4* src = (const float4*)(S + (size_t)row * DIM);
        float4 v0 = src[lane * 2], v1 = src[lane * 2 + 1];
        float a = rbf(v0.x), b = rbf(v0.y), c = rbf(v0.z), d = rbf(v0.w);
        float e = rbf(v1.x), f = rbf(v1.y), g = rbf(v1.z), h = rbf(v1.w);
        float ss = a * a + b * b + c * c + d * d + e * e + f * f + g * g + h * h;
        uint4 pk = make_uint4(packbf(v0.x, v0.y), packbf(v0.z, v0.w),
                              packbf(v1.x, v1.y), packbf(v1.z, v1.w));
        ((uint4*)(g_Sb + (size_t)row * DIM))[lane] = pk;
#pragma unroll
        for (int m = 16; m >= 1; m >>= 1) ss += __shfl_xor_sync(0xffffffffu, ss, m);
        if (lane == 0) g_s2[row] = ss;
    }
}

// ---------------------------------------------------------------------------
// Main: bf16 m16n8k16 GEMM with ks-level fragment pipelining + fused epilogue
// ---------------------------------------------------------------------------
__global__ __launch_bounds__(256, 2)
void dcl_main_kernel(const float* __restrict__ T, float* __restrict__ out) {
    extern __shared__ char smem[];
    const uint32_t sb = smem_u32(smem);

    const int tid   = threadIdx.x;
    const int lane  = tid & 31;
    const int warp  = tid >> 5;
    const int warpM = warp & 1;        // 2 warps along M (64 rows)
    const int warpN = warp >> 1;       // 4 warps along N (32 cols)
    const int rowBase = blockIdx.y * BM;
    const int colBase = blockIdx.x * BN;

    const int mrow  = lane & 7;
    const int matLo = (lane >> 3) & 1;
    const int matHi = (lane >> 4) & 1;

    float* aux  = (float*)(smem + OFF_AUX);
    float* c2s  = aux;
    float* s2s  = aux + 128;
    float* rowP = aux + 256;
    float* colP = aux + 384;
    if (tid < 128) {
        c2s[tid] = g_c2[rowBase + tid];
        s2s[tid] = g_s2[colBase + tid];
        rowP[tid] = 0.0f;
        colP[tid] = 0.0f;
    }

    const uint32_t aB[2] = { sb + OFF_A0, sb + OFF_A1 };
    const uint32_t bB[2] = { sb + OFF_B0, sb + OFF_B1 };

    float acc[4][4][4];
#pragma unroll
    for (int mi = 0; mi < 4; mi++)
#pragma unroll
        for (int ni = 0; ni < 4; ni++)
#pragma unroll
            for (int c = 0; c < 4; c++) acc[mi][ni][c] = 0.0f;

    auto fill = [&](int buf, int ch) {
#pragma unroll
        for (int t = 0; t < 4; t++) {
            int idx = tid + t * 256;
            int r = idx >> 3, g = idx & 7;
            cp16(aB[buf] + swz((uint32_t)(r * 128 + g * 16)),
                 g_Cb + (size_t)(rowBase + r) * DIM + ch * BKC + g * 8);
        }
#pragma unroll
        for (int t = 0; t < 4; t++) {
            int idx = tid + t * 256;
            int r = idx >> 3, g = idx & 7;
            cp16(bB[buf] + swz((uint32_t)(r * 128 + g * 16)),
                 g_Sb + (size_t)(colBase + r) * DIM + ch * BKC + g * 8);
        }
        asm volatile("cp.async.commit_group;" ::: "memory");
    };

    fill(0, 0);
    fill(1, 1);

    const uint32_t aRowOff = (uint32_t)(warpM * 64 + matLo * 8 + mrow) * 128;
    const uint32_t bRowOff = (uint32_t)(warpN * 32 + matHi * 8 + mrow) * 128;

    uint32_t a[2][4][4], b[2][4][2];

    auto ldfrag = [&](int slot, uint32_t ab, uint32_t bb, int ks) {
        const uint32_t ca = (uint32_t)((((ks << 1) | matHi) ^ mrow) << 4);
        const uint32_t cb = (uint32_t)((((ks << 1) | matLo) ^ mrow) << 4);
#pragma unroll
        for (int mi = 0; mi < 4; mi++)
            ldsm4(a[slot][mi], ab + mi * 2048 + ca);
#pragma unroll
        for (int p = 0; p < 2; p++) {
            uint32_t r[4];
            ldsm4(r, bb + p * 2048 + cb);
            b[slot][2 * p][0] = r[0]; b[slot][2 * p][1] = r[1];
            b[slot][2 * p + 1][0] = r[2]; b[slot][2 * p + 1][1] = r[3];
        }
    };

#pragma unroll
    for (int ch = 0; ch < NCHUNK; ch++) {
        if (ch < NCHUNK - 1) asm volatile("cp.async.wait_group 1;" ::: "memory");
        else                 asm volatile("cp.async.wait_group 0;" ::: "memory");
        __syncthreads();

        const uint32_t ab = aB[ch & 1] + aRowOff;
        const uint32_t bb = bB[ch & 1] + bRowOff;

        ldfrag(0, ab, bb, 0);
#pragma unroll
        for (int ks = 0; ks < 4; ks++) {
            const int cur = ks & 1;
            if (ks < 3) ldfrag(cur ^ 1, ab, bb, ks + 1);
#pragma unroll
            for (int mi = 0; mi < 4; mi++)
#pragma unroll
                for (int ni = 0; ni < 4; ni++)
                    mma_bf16(acc[mi][ni], a[cur][mi], b[cur][ni]);
        }

        if (ch + 2 < NCHUNK) {
            __syncthreads();          // all warps done reading buf (ch&1)
            fill(ch & 1, ch + 2);
        }
    }

    // ---------------- epilogue ----------------
    __syncthreads();

    // e = exp(-dist * expT) = ex2(dist * kk), kk = -expT*log2(e)
    const float kk = -__expf(T[0]) * LOG2EF;
    const bool diagCTA = (blockIdx.x == blockIdx.y);
    const int g   = lane >> 2;
    const int tig = lane & 3;

    float rAcc[8], cAcc[8];
#pragma unroll
    for (int i = 0; i < 8; i++) { rAcc[i] = 0.0f; cAcc[i] = 0.0f; }
    float dloc = 0.0f;   // sum of f = sim/ln2 on diagonal

#pragma unroll
    for (int mi = 0; mi < 4; mi++) {
#pragma unroll
        for (int ni = 0; ni < 4; ni++) {
#pragma unroll
            for (int c = 0; c < 4; c++) {
                const int h   = c >> 1;
                const int bb2 = c & 1;
                const int rl = warpM * 64 + mi * 16 + g + h * 8;
                const int cl = warpN * 32 + ni * 8 + tig * 2 + bb2;
                float d2 = fmaxf(fmaf(-2.0f, acc[mi][ni][c], c2s[rl] + s2s[cl]), 0.0f);
                float dist;
                asm("sqrt.approx.f32 %0, %1;" : "=f"(dist) : "f"(d2));
                float f = dist * kk;
                float e;
                asm("ex2.approx.f32 %0, %1;" : "=f"(e) : "f"(f));
                rAcc[mi * 2 + h] += e;
                cAcc[ni * 2 + bb2] += e;
                if (diagCTA && rl == cl) dloc += f;
            }
        }
    }

#pragma unroll
    for (int i = 0; i < 8; i++) {
        float v = rAcc[i];
        v += __shfl_xor_sync(0xffffffffu, v, 1);
        v += __shfl_xor_sync(0xffffffffu, v, 2);
        if (tig == 0) {
            int mi = i >> 1, h = i & 1;
            atomicAdd(&rowP[warpM * 64 + mi * 16 + h * 8 + g], v);
        }
    }
#pragma unroll
    for (int i = 0; i < 8; i++) {
        float v = cAcc[i];
        v += __shfl_xor_sync(0xffffffffu, v, 4);
        v += __shfl_xor_sync(0xffffffffu, v, 8);
        v += __shfl_xor_sync(0xffffffffu, v, 16);
        if (g == 0) {
            int ni = i >> 1, bb2 = i & 1;
            atomicAdd(&colP[warpN * 32 + ni * 8 + tig * 2 + bb2], v);
        }
    }

    if (diagCTA) {
#pragma unroll
        for (int m = 16; m >= 1; m >>= 1)
            dloc += __shfl_xor_sync(0xffffffffu, dloc, m);
        if (lane == 0) atomicAdd(out, -dloc * (LN2F / (float)NPTS));
    }

    __syncthreads();
    if (tid < 128) {
        atomicAdd(&g_rowsum[rowBase + tid], rowP[tid]);
        atomicAdd(&g_colsum[colBase + tid], colP[tid]);
    }
}

// ---------------------------------------------------------------------------
__global__ void dcl_final_kernel(float* __restrict__ out) {
    int i = blockIdx.x * blockDim.x + threadIdx.x;
    float v = logf(g_rowsum[i]) + logf(g_colsum[i]);
#pragma unroll
    for (int m = 16; m >= 1; m >>= 1) v += __shfl_xor_sync(0xffffffffu, v, m);
    if ((threadIdx.x & 31) == 0)
        atomicAdd(out, v * (0.5f / (float)NPTS));
}

// ---------------------------------------------------------------------------
extern "C" void kernel_launch(void* const* d_in, const int* in_sizes, int n_in,
                              void* d_out, int out_size) {
    const float* C = (const float*)d_in[0];
    const float* S = (const float*)d_in[1];
    const float* T = (const float*)d_in[2];
    float* out = (float*)d_out;

    static bool attr_set = false;
    if (!attr_set) {
        cudaFuncSetAttribute(dcl_main_kernel,
                             cudaFuncAttributeMaxDynamicSharedMemorySize, SMEM_TOTAL);
        attr_set = true;
    }

    dcl_prep_kernel<<<NPTS / 8, 256>>>(C, S, out);
    dim3 grid(NPTS / BN, NPTS / BM);
    dcl_main_kernel<<<grid, 256, SMEM_TOTAL>>>(T, out);
    dcl_final_kernel<<<NPTS / 1024, 1024>>>(out);
}